// round 16
// baseline (speedup 1.0000x reference)
#include <cuda_runtime.h>
#include <cuda_bf16.h>
#include <cstdint>

#define BB 16
#define NN 4096
#define CC 64
#define NPT 1024
#define NSMP 32
#define NFPS 8   // FPS blocks; each handles 2 batches

typedef unsigned long long u64;
typedef unsigned int u32;

#define WKLD 72   // K-major weight image leading dim (bf16 elems): conflict-free

// ---------------- scratch (device globals; no allocations allowed) ----------
__device__ __align__(16) float g_pre1[BB * NN * CC];   // 16 MB
__device__ float g_new_xyz[BB * NPT * 3];
__device__ int   g_idx[BB * NPT * NSMP];
// K-major padded bf16 weights: W2T hi(0) lo(9216); W3T hi(18432) lo(36864)
__device__ __align__(16) unsigned char g_wimg[55296];

// ---------------- helpers ---------------------------------------------------
__device__ __forceinline__ unsigned redux_max_u32(unsigned v) {
    unsigned r; asm("redux.sync.max.u32 %0, %1, 0xffffffff;" : "=r"(r) : "r"(v)); return r;
}
__device__ __forceinline__ unsigned redux_min_u32(unsigned v) {
    unsigned r; asm("redux.sync.min.u32 %0, %1, 0xffffffff;" : "=r"(r) : "r"(v)); return r;
}
__device__ __forceinline__ u64 pack2(float lo, float hi) {
    u64 r; asm("mov.b64 %0, {%1, %2};" : "=l"(r) : "f"(lo), "f"(hi)); return r;
}
__device__ __forceinline__ void unpack2(u64 v, float& lo, float& hi) {
    asm("mov.b64 {%0, %1}, %2;" : "=f"(lo), "=f"(hi) : "l"(v));
}
__device__ __forceinline__ u64 add2(u64 a, u64 b) {
    u64 r; asm("add.rn.f32x2 %0, %1, %2;" : "=l"(r) : "l"(a), "l"(b)); return r;
}
__device__ __forceinline__ u64 mul2(u64 a, u64 b) {
    u64 r; asm("mul.rn.f32x2 %0, %1, %2;" : "=l"(r) : "l"(a), "l"(b)); return r;
}
// packed bf16x2: first arg -> upper 16 bits, second -> lower
__device__ __forceinline__ u32 cvt_bf16x2(float hi_src, float lo_src) {
    u32 r; asm("cvt.rn.satfinite.bf16x2.f32 %0, %1, %2;" : "=r"(r) : "f"(hi_src), "f"(lo_src)); return r;
}
// mma.m16n8k16 row.col bf16 -> f32, D += A*B
__device__ __forceinline__ void mma16816(float* c, const u32* a, u32 b0, u32 b1) {
    asm volatile(
        "mma.sync.aligned.m16n8k16.row.col.f32.bf16.bf16.f32 "
        "{%0,%1,%2,%3}, {%4,%5,%6,%7}, {%8,%9}, {%0,%1,%2,%3};"
        : "+f"(c[0]), "+f"(c[1]), "+f"(c[2]), "+f"(c[3])
        : "r"(a[0]), "r"(a[1]), "r"(a[2]), "r"(a[3]), "r"(b0), "r"(b1));
}
__device__ __forceinline__ void ldm4(u32& r0, u32& r1, u32& r2, u32& r3, u32 saddr) {
    asm volatile("ldmatrix.sync.aligned.m8n8.x4.shared.b16 {%0,%1,%2,%3}, [%4];"
        : "=r"(r0), "=r"(r1), "=r"(r2), "=r"(r3) : "r"(saddr));
}
__device__ __forceinline__ u32 smem_u32(const void* p) {
    return (u32)__cvta_generic_to_shared(p);
}
__device__ __forceinline__ float low_of(u32 hi)  { return __uint_as_float(hi << 16); }
__device__ __forceinline__ float high_of(u32 hi) { return __uint_as_float(hi & 0xffff0000u); }

// ---------------------------------------------------------------------------
// K0: prep — W2^T / W3^T (K-major rows, padded WKLD) split into bf16 hi/lo
// ---------------------------------------------------------------------------
extern "C" __global__ void k_prep(const float* __restrict__ W2, const float* __restrict__ W3)
{
    int tid = blockIdx.x * blockDim.x + threadIdx.x;
    __nv_bfloat16* w2h = (__nv_bfloat16*)(g_wimg);
    __nv_bfloat16* w2l = (__nv_bfloat16*)(g_wimg + 9216);
    __nv_bfloat16* w3h = (__nv_bfloat16*)(g_wimg + 18432);
    __nv_bfloat16* w3l = (__nv_bfloat16*)(g_wimg + 36864);
    for (int e = tid; e < 64 * 64; e += gridDim.x * blockDim.x) {
        int k = e >> 6, n = e & 63;
        float v = W2[e];                       // W2[k][n]
        __nv_bfloat16 hb = __float2bfloat16(v);
        float hf = __bfloat162float(hb);
        w2h[n * WKLD + k] = hb;
        w2l[n * WKLD + k] = __float2bfloat16(v - hf);
    }
    for (int e = tid; e < 64 * 128; e += gridDim.x * blockDim.x) {
        int k = e >> 7, n = e & 127;
        float v = W3[e];                       // W3[k][n]
        __nv_bfloat16 hb = __float2bfloat16(v);
        float hf = __bfloat162float(hb);
        w3h[n * WKLD + k] = hb;
        w3l[n * WKLD + k] = __float2bfloat16(v - hf);
    }
}

// ---------------------------------------------------------------------------
// K1: blocks [0,8): FPS for TWO batches each (2b, 2b+1), interleaved steps —
//     one __syncthreads amortized over both batches' reductions.
//     blocks [8,..): pre1.
// FPS smem (floats): sx/sy/sz per batch q at q*12288 (+0,+4096,+8192);
//   spair (uint2) at float-offset 24576: batch q at +q*64 B... laid below;
//   sfps at 24704 (2 x 1024 ints). total 26752 floats = 107008 B.
// ---------------------------------------------------------------------------
extern "C" __global__ void __launch_bounds__(512)
k_fps_pre1(const float* __restrict__ xyz, const float* __restrict__ points,
           const float* __restrict__ W1, float* __restrict__ out_xyz)
{
    extern __shared__ float sm[];
    int t = threadIdx.x;

    if (blockIdx.x < NFPS) {
        float* sx[2]; float* sy[2]; float* sz[2];
        uint2* spair[2];
        int* sfps[2];
        #pragma unroll
        for (int q = 0; q < 2; q++) {
            sx[q] = sm + q * 12288;
            sy[q] = sm + q * 12288 + 4096;
            sz[q] = sm + q * 12288 + 8192;
            spair[q] = (uint2*)(sm + 24576) + q * 32;   // 2 bufs x 16
            sfps[q] = (int*)(sm + 24704) + q * NPT;
        }

        // stage both batches' coordinates (SoA)
        #pragma unroll
        for (int q = 0; q < 2; q++) {
            int b = blockIdx.x * 2 + q;
            const float* xb = xyz + (size_t)b * NN * 3;
            for (int i = t; i < NN * 3; i += 512) {
                int n = i / 3, c = i - n * 3;
                float v = xb[i];
                ((c == 0) ? sx[q] : (c == 1) ? sy[q] : sz[q])[n] = v;
            }
        }
        __syncthreads();

        float dd[2][8];
        u64 PX[2][4], PY[2][4], PZ[2][4];
        #pragma unroll
        for (int q = 0; q < 2; q++)
            #pragma unroll
            for (int a = 0; a < 4; a++) {
                int p0 = t + (2 * a) * 512, p1 = t + (2 * a + 1) * 512;
                PX[q][a] = pack2(sx[q][p0], sx[q][p1]);
                PY[q][a] = pack2(sy[q][p0], sy[q][p1]);
                PZ[q][a] = pack2(sz[q][p0], sz[q][p1]);
                dd[q][2 * a] = 1e10f; dd[q][2 * a + 1] = 1e10f;
            }

        int warp = t >> 5, lane = t & 31;
        int far[2] = {0, 0};
        float cx[2], cy[2], cz[2];
        #pragma unroll
        for (int q = 0; q < 2; q++) { cx[q] = sx[q][0]; cy[q] = sy[q][0]; cz[q] = sz[q][0]; }

        for (int s = 0; s < NPT; s++) {
            if (t == 0) { sfps[0][s] = far[0]; sfps[1][s] = far[1]; }

            // ---- local phase: both batches (independent -> overlap) ----
            #pragma unroll
            for (int q = 0; q < 2; q++) {
                u64 ncx = pack2(-cx[q], -cx[q]);
                u64 ncy = pack2(-cy[q], -cy[q]);
                u64 ncz = pack2(-cz[q], -cz[q]);

                unsigned lb = 0; int li = t;
                #pragma unroll
                for (int a = 0; a < 4; a++) {
                    u64 dx = add2(PX[q][a], ncx);
                    u64 dy = add2(PY[q][a], ncy);
                    u64 dz = add2(PZ[q][a], ncz);
                    u64 d2 = add2(add2(mul2(dx, dx), mul2(dy, dy)), mul2(dz, dz));
                    float dlo, dhi;
                    unpack2(d2, dlo, dhi);
                    dd[q][2 * a]     = fminf(dd[q][2 * a], dlo);
                    dd[q][2 * a + 1] = fminf(dd[q][2 * a + 1], dhi);
                    unsigned blo = __float_as_uint(dd[q][2 * a]);     // dd>=0: monotone
                    unsigned bhi = __float_as_uint(dd[q][2 * a + 1]);
                    if (a == 0) { lb = blo; li = t; }
                    else if (blo > lb) { lb = blo; li = t + (2 * a) * 512; }
                    if (bhi > lb) { lb = bhi; li = t + (2 * a + 1) * 512; }
                }
                unsigned wmax = redux_max_u32(lb);
                unsigned cand = (lb == wmax) ? (unsigned)li : 0xffffffffu;
                unsigned wbesti = redux_min_u32(cand);
                if (lane == 0) spair[q][(s & 1) * 16 + warp] = make_uint2(wmax, wbesti);
            }
            __syncthreads();
            // ---- final phase: every warp redundantly reduces 16 entries ----
            #pragma unroll
            for (int q = 0; q < 2; q++) {
                uint2 pr = spair[q][(s & 1) * 16 + (lane & 15)];
                unsigned gmax = redux_max_u32(pr.x);
                unsigned c2 = (pr.x == gmax) ? pr.y : 0xffffffffu;
                far[q] = (int)redux_min_u32(c2);
                cx[q] = sx[q][far[q]]; cy[q] = sy[q][far[q]]; cz[q] = sz[q][far[q]];
            }
        }
        __syncthreads();

        // gather new_xyz: thread t handles centroids t and t+512 of both batches
        #pragma unroll
        for (int q = 0; q < 2; q++) {
            int b = blockIdx.x * 2 + q;
            #pragma unroll
            for (int hh = 0; hh < 2; hh++) {
                int sc = t + hh * 512;
                int fi = sfps[q][sc];
                int o = (b * NPT + sc) * 3;
                float nx = sx[q][fi], ny = sy[q][fi], nz = sz[q][fi];
                g_new_xyz[o] = nx; g_new_xyz[o + 1] = ny; g_new_xyz[o + 2] = nz;
                out_xyz[o] = nx; out_xyz[o + 1] = ny; out_xyz[o + 2] = nz;
            }
        }
    } else {
        // ---------------- pre1 ----------------
        float* W1s = sm;
        for (int i = t; i < 67 * 64; i += 512) W1s[i] = W1[i];
        __syncthreads();
        int nb = gridDim.x - NFPS;
        const int total = BB * NN * CC;
        for (int e = (blockIdx.x - NFPS) * 512 + t; e < total; e += nb * 512) {
            int r = e >> 6;
            int d = e & 63;
            const float* xr = xyz + (size_t)r * 3;
            float acc = fmaf(xr[2], W1s[2 * 64 + d],
                        fmaf(xr[1], W1s[1 * 64 + d], xr[0] * W1s[d]));
            const float* pr = points + (size_t)r * 64;
            #pragma unroll 8
            for (int c = 0; c < 64; c++)
                acc = fmaf(pr[c], W1s[(3 + c) * 64 + d], acc);
            g_pre1[e] = acc;
        }
    }
}

// ---------------------------------------------------------------------------
// K2: query_ball — 128 blocks x 512 thr (unchanged)
// ---------------------------------------------------------------------------
extern "C" __global__ void __launch_bounds__(512)
k_query(const float* __restrict__ xyz, float* __restrict__ out_idx)
{
    extern __shared__ float sm[];
    float* sx = sm;
    float* sy = sm + NN;
    float* sz = sm + 2 * NN;
    int b = blockIdx.x >> 3;
    int sub = blockIdx.x & 7;

    const float* xb = xyz + (size_t)b * NN * 3;
    for (int i = threadIdx.x; i < NN * 3; i += 512) {
        int n = i / 3, c = i - n * 3;
        ((c == 0) ? sx : (c == 1) ? sy : sz)[n] = xb[i];
    }
    __syncthreads();

    int warp = threadIdx.x >> 5, lane = threadIdx.x & 31;
    const float R2 = 0.04f;

    for (int q = 0; q < 8; q++) {
        int s = sub * 128 + warp * 8 + q;
        int cb = b * NPT + s;
        float cx = g_new_xyz[cb * 3], cy = g_new_xyz[cb * 3 + 1], cz = g_new_xyz[cb * 3 + 2];
        int base = cb * NSMP;
        int cnt = 0, first = 0;
        for (int ch = 0; ch < NN / 32; ch++) {
            int p = ch * 32 + lane;
            float dx = __fadd_rn(sx[p], -cx);
            float dy = __fadd_rn(sy[p], -cy);
            float dz = __fadd_rn(sz[p], -cz);
            float d = __fadd_rn(__fadd_rn(__fmul_rn(dx, dx), __fmul_rn(dy, dy)),
                                __fmul_rn(dz, dz));
            bool ok = (d <= R2);
            unsigned m = __ballot_sync(0xffffffffu, ok);
            if (m) {
                if (cnt == 0) first = ch * 32 + __ffs(m) - 1;
                int pos = cnt + __popc(m & ((1u << lane) - 1u));
                if (ok && pos < NSMP) {
                    g_idx[base + pos] = p;
                    out_idx[base + pos] = (float)p;
                }
                cnt += __popc(m);
                if (cnt >= NSMP) break;
            }
        }
        if (cnt < NSMP) {
            int slot = cnt + lane;
            if (slot < NSMP) {
                g_idx[base + slot] = first;
                out_idx[base + slot] = (float)first;
            }
        }
    }
}

// ---------------------------------------------------------------------------
// K3: raw mma.m16n8k16 MLP, fragment-chained, ldmatrix.x4 B loads (unchanged)
// ---------------------------------------------------------------------------
extern "C" __global__ void __launch_bounds__(128, 3)
k_mlp_mma(const float* __restrict__ W1, const float* __restrict__ b1,
          const float* __restrict__ b2, const float* __restrict__ b3,
          float* __restrict__ out_pts)
{
    extern __shared__ __align__(16) char smc[];
    int tid = threadIdx.x;
    int wid = tid >> 5, lane = tid & 31;
    int gid = lane >> 2, tidg = lane & 3;

    float* b2s  = (float*)(smc + 55296);
    float* b3s  = (float*)(smc + 55552);
    float* W1x  = (float*)(smc + 56064);
    float* b1s  = (float*)(smc + 56832);
    float* coffs = (float*)(smc + 57088);

    {
        const float4* src = (const float4*)g_wimg;
        float4* dst = (float4*)smc;
        for (int i = tid; i < 3456; i += 128) dst[i] = src[i];
        if (tid < 64) {
            b2s[tid] = b2[tid];
            b1s[tid] = b1[tid];
            W1x[tid] = W1[tid]; W1x[64 + tid] = W1[64 + tid]; W1x[128 + tid] = W1[128 + tid];
        }
        b3s[tid] = b3[tid];
    }
    __syncthreads();

    u32 sbase = smem_u32(smc);
    u32 w2h_s = sbase, w2l_s = sbase + 9216;
    u32 w3h_s = sbase + 18432, w3l_s = sbase + 36864;
    int lt = lane >> 3, lr = lane & 7;
    u32 lro = (u32)(((lt >> 1) * 8 + lr) * (WKLD * 2) + (lt & 1) * 16);

    for (int it = 0; it < 4; it++) {
        int cent = (blockIdx.x * 4 + it) * 4 + wid;
        int b = cent >> 10;

        float ccx = g_new_xyz[cent * 3], ccy = g_new_xyz[cent * 3 + 1], ccz = g_new_xyz[cent * 3 + 2];
        float* co = coffs + wid * 64;
        #pragma unroll
        for (int r = 0; r < 2; r++) {
            int d = lane + r * 32;
            co[d] = b1s[d] - (ccx * W1x[d] + ccy * W1x[64 + d] + ccz * W1x[128 + d]);
        }
        __syncwarp();

        int p = g_idx[cent * NSMP + lane];
        const float* rowp[4];
        #pragma unroll
        for (int j = 0; j < 4; j++) {
            int pj = __shfl_sync(0xffffffffu, p, gid + 8 * j);
            rowp[j] = g_pre1 + ((size_t)(b * NN + pj)) * 64;
        }

        u32 a1H[2][4][4], a1L[2][4][4];
        #pragma unroll
        for (int mt = 0; mt < 2; mt++) {
            #pragma unroll
            for (int kb = 0; kb < 4; kb++) {
                int cA = 2 * tidg + 16 * kb;
                float2 coA = *(float2*)&co[cA];
                float2 coB = *(float2*)&co[cA + 8];
                #pragma unroll
                for (int rr = 0; rr < 4; rr++) {
                    const float* rp = rowp[mt * 2 + (rr & 1)];
                    int col = cA + ((rr >> 1) ? 8 : 0);
                    float2 cv = (rr >> 1) ? coB : coA;
                    float2 v = *(const float2*)(rp + col);
                    float h0 = fmaxf(v.x + cv.x, 0.0f);
                    float h1 = fmaxf(v.y + cv.y, 0.0f);
                    u32 hi = cvt_bf16x2(h1, h0);
                    a1H[mt][kb][rr] = hi;
                    a1L[mt][kb][rr] = cvt_bf16x2(h1 - high_of(hi), h0 - low_of(hi));
                }
            }
        }

        float acc2[2][8][4];
        #pragma unroll
        for (int mt = 0; mt < 2; mt++)
            #pragma unroll
            for (int nt = 0; nt < 8; nt++)
                #pragma unroll
                for (int r = 0; r < 4; r++) acc2[mt][nt][r] = 0.0f;

        #pragma unroll
        for (int kb = 0; kb < 4; kb++) {
            #pragma unroll
            for (int ntp = 0; ntp < 8; ntp += 2) {
                u32 off = (u32)(ntp * (8 * WKLD * 2) + kb * 32) + lro;
                u32 bh0, bh1, bh2, bh3, bl0, bl1, bl2, bl3;
                ldm4(bh0, bh1, bh2, bh3, w2h_s + off);
                ldm4(bl0, bl1, bl2, bl3, w2l_s + off);
                #pragma unroll
                for (int mt = 0; mt < 2; mt++) {
                    mma16816(acc2[mt][ntp], a1H[mt][kb], bh0, bh1);
                    mma16816(acc2[mt][ntp], a1H[mt][kb], bl0, bl1);
                    mma16816(acc2[mt][ntp], a1L[mt][kb], bh0, bh1);
                    mma16816(acc2[mt][ntp + 1], a1H[mt][kb], bh2, bh3);
                    mma16816(acc2[mt][ntp + 1], a1H[mt][kb], bl2, bl3);
                    mma16816(acc2[mt][ntp + 1], a1L[mt][kb], bh2, bh3);
                }
            }
        }

        u32 a3H[2][4][4], a3L[2][4][4];
        #pragma unroll
        for (int mt = 0; mt < 2; mt++) {
            #pragma unroll
            for (int kb = 0; kb < 4; kb++) {
                #pragma unroll
                for (int half = 0; half < 2; half++) {
                    int nt = 2 * kb + half;
                    float2 bb = *(float2*)&b2s[8 * nt + 2 * tidg];
                    #pragma unroll
                    for (int rp = 0; rp < 2; rp++) {
                        float h0 = fmaxf(acc2[mt][nt][2 * rp]     + bb.x, 0.0f);
                        float h1 = fmaxf(acc2[mt][nt][2 * rp + 1] + bb.y, 0.0f);
                        u32 hi = cvt_bf16x2(h1, h0);
                        int r = half * 2 + rp;
                        a3H[mt][kb][r] = hi;
                        a3L[mt][kb][r] = cvt_bf16x2(h1 - high_of(hi), h0 - low_of(hi));
                    }
                }
            }
        }

        #pragma unroll
        for (int half = 0; half < 2; half++) {
            u32 w3h_b = w3h_s + half * (64 * WKLD * 2);
            u32 w3l_b = w3l_s + half * (64 * WKLD * 2);
            float acc3[2][8][4];
            #pragma unroll
            for (int mt = 0; mt < 2; mt++)
                #pragma unroll
                for (int nt = 0; nt < 8; nt++)
                    #pragma unroll
                    for (int r = 0; r < 4; r++) acc3[mt][nt][r] = 0.0f;

            #pragma unroll
            for (int kb = 0; kb < 4; kb++) {
                #pragma unroll
                for (int ntp = 0; ntp < 8; ntp += 2) {
                    u32 off = (u32)(ntp * (8 * WKLD * 2) + kb * 32) + lro;
                    u32 bh0, bh1, bh2, bh3, bl0, bl1, bl2, bl3;
                    ldm4(bh0, bh1, bh2, bh3, w3h_b + off);
                    ldm4(bl0, bl1, bl2, bl3, w3l_b + off);
                    #pragma unroll
                    for (int mt = 0; mt < 2; mt++) {
                        mma16816(acc3[mt][ntp], a3H[mt][kb], bh0, bh1);
                        mma16816(acc3[mt][ntp], a3H[mt][kb], bl0, bl1);
                        mma16816(acc3[mt][ntp], a3L[mt][kb], bh0, bh1);
                        mma16816(acc3[mt][ntp + 1], a3H[mt][kb], bh2, bh3);
                        mma16816(acc3[mt][ntp + 1], a3H[mt][kb], bl2, bl3);
                        mma16816(acc3[mt][ntp + 1], a3L[mt][kb], bh2, bh3);
                    }
                }
            }

            #pragma unroll
            for (int nt = 0; nt < 8; nt++) {
                float2 bb = *(float2*)&b3s[64 * half + 8 * nt + 2 * tidg];
                float me = 0.0f, mo = 0.0f;   // relu lower bound
                #pragma unroll
                for (int mt = 0; mt < 2; mt++) {
                    me = fmaxf(me, fmaxf(acc3[mt][nt][0] + bb.x, acc3[mt][nt][2] + bb.x));
                    mo = fmaxf(mo, fmaxf(acc3[mt][nt][1] + bb.y, acc3[mt][nt][3] + bb.y));
                }
                #pragma unroll
                for (int d = 4; d <= 16; d <<= 1) {
                    me = fmaxf(me, __shfl_xor_sync(0xffffffffu, me, d));
                    mo = fmaxf(mo, __shfl_xor_sync(0xffffffffu, mo, d));
                }
                if (gid == 0) {
                    int o = cent * 128 + 64 * half + 8 * nt + 2 * tidg;
                    out_pts[o] = me;
                    out_pts[o + 1] = mo;
                }
            }
        }
    }
}

// ---------------------------------------------------------------------------
extern "C" void kernel_launch(void* const* d_in, const int* in_sizes, int n_in,
                              void* d_out, int out_size)
{
    const float* xyz    = (const float*)d_in[0];
    const float* points = (const float*)d_in[1];
    const float* W1     = (const float*)d_in[2];
    const float* b1     = (const float*)d_in[3];
    const float* W2     = (const float*)d_in[4];
    const float* b2     = (const float*)d_in[5];
    const float* W3     = (const float*)d_in[6];
    const float* b3     = (const float*)d_in[7];

    float* out = (float*)d_out;
    float* out_xyz = out;
    float* out_pts = out + BB * NPT * 3;
    float* out_idx = out + BB * NPT * 3 + BB * NPT * 128;

    cudaFuncSetAttribute(k_fps_pre1, cudaFuncAttributeMaxDynamicSharedMemorySize, 107008);
    cudaFuncSetAttribute(k_query,    cudaFuncAttributeMaxDynamicSharedMemorySize, 49152);
    cudaFuncSetAttribute(k_mlp_mma,  cudaFuncAttributeMaxDynamicSharedMemorySize, 58368);

    k_prep<<<8, 256>>>(W2, W3);
    k_fps_pre1<<<156, 512, 107008>>>(xyz, points, W1, out_xyz);
    k_query<<<128, 512, 49152>>>(xyz, out_idx);
    k_mlp_mma<<<1024, 128, 58368>>>(W1, b1, b2, b3, out_pts);
}